// round 13
// baseline (speedup 1.0000x reference)
#include <cuda_runtime.h>
#include <cuda_bf16.h>
#include <cstdint>

// Scratch (no allocation allowed). Zero-initialized at module load; the
// scatter's last block restores zeros each call (deterministic replays).
__device__ double             g_sums[3];
__device__ unsigned long long g_cnts[3];
__device__ unsigned           g_done;

__device__ __forceinline__ uint32_t smem_u32(const void* p) {
    uint32_t a;
    asm("{ .reg .u64 t; cvta.to.shared.u64 t, %1; cvt.u32.u64 %0, t; }"
        : "=r"(a) : "l"(p));
    return a;
}

// ---------------------------------------------------------------------------
// Per-item accumulate: 4 pixels (1 int4 + 3 float4).
// ---------------------------------------------------------------------------
__device__ __forceinline__ void acc_item(const int4& cls,
                                         const float4& a, const float4& b,
                                         const float4& d,
                                         float& ptot, float& s0, float& s1,
                                         unsigned& c0, unsigned& c1) {
    float p0 = a.x + a.y + a.z;
    float p1 = a.w + b.x + b.y;
    float p2 = b.z + b.w + d.x;
    float p3 = d.y + d.z + d.w;
    ptot += (p0 + p1) + (p2 + p3);
    s0 += (cls.x == 0) ? p0 : 0.f;  c0 += (cls.x == 0);
    s1 += (cls.x == 1) ? p0 : 0.f;  c1 += (cls.x == 1);
    s0 += (cls.y == 0) ? p1 : 0.f;  c0 += (cls.y == 0);
    s1 += (cls.y == 1) ? p1 : 0.f;  c1 += (cls.y == 1);
    s0 += (cls.z == 0) ? p2 : 0.f;  c0 += (cls.z == 0);
    s1 += (cls.z == 1) ? p2 : 0.f;  c1 += (cls.z == 1);
    s0 += (cls.w == 0) ? p3 : 0.f;  c0 += (cls.w == 0);
    s1 += (cls.w == 1) ? p3 : 0.f;  c1 += (cls.w == 1);
}

// ---------------------------------------------------------------------------
// Kernel 1: grid-stride reduction, 2x unrolled, front-batched loads.
// After the main loop, trigger the dependent scatter launch so its block
// dispatch + inst prefetch overlaps this kernel's reduction epilogue.
// ---------------------------------------------------------------------------
__global__ __launch_bounds__(256)
void iwap_reduce_kernel(const float4* __restrict__ feats4,
                        const int4*  __restrict__ inst4,
                        const float* __restrict__ feats,
                        const int*   __restrict__ inst,
                        int nitems, int npix) {
    float    ptot = 0.f, s0 = 0.f, s1 = 0.f;
    unsigned c0 = 0, c1 = 0, nit = 0;

    const int S = gridDim.x * blockDim.x;
    int i = blockIdx.x * blockDim.x + threadIdx.x;

    for (; i + S < nitems; i += 2 * S) {
        int4   clsA = __ldg(&inst4[i]);
        int4   clsB = __ldg(&inst4[i + S]);
        float4 a0 = __ldcs(&feats4[3 * i + 0]);
        float4 a1 = __ldcs(&feats4[3 * i + 1]);
        float4 a2 = __ldcs(&feats4[3 * i + 2]);
        float4 b0 = __ldcs(&feats4[3 * (i + S) + 0]);
        float4 b1 = __ldcs(&feats4[3 * (i + S) + 1]);
        float4 b2 = __ldcs(&feats4[3 * (i + S) + 2]);
        acc_item(clsA, a0, a1, a2, ptot, s0, s1, c0, c1);
        acc_item(clsB, b0, b1, b2, ptot, s0, s1, c0, c1);
        nit += 2;
    }
    if (i < nitems) {
        int4   cls = __ldg(&inst4[i]);
        float4 a0 = __ldcs(&feats4[3 * i + 0]);
        float4 a1 = __ldcs(&feats4[3 * i + 1]);
        float4 a2 = __ldcs(&feats4[3 * i + 2]);
        acc_item(cls, a0, a1, a2, ptot, s0, s1, c0, c1);
        nit += 1;
    }

    // Main streaming done: allow the dependent scatter to start dispatching.
    // (Its pre-sync prologue only loads inst — input data, no hazard.)
    cudaTriggerProgrammaticLaunchCompletion();

    // Tail pixels (npix not divisible by 4) by thread 0 of block 0.
    unsigned ntail = 0;
    if (blockIdx.x == 0 && threadIdx.x == 0) {
        for (int p = nitems * 4; p < npix; p++) {
            int   c  = inst[p];
            float ps = feats[3 * p] + feats[3 * p + 1] + feats[3 * p + 2];
            ptot += ps; ntail++;
            if      (c == 0) { s0 += ps; c0++; }
            else if (c == 1) { s1 += ps; c1++; }
        }
    }

    float    s2 = ptot - s0 - s1;
    unsigned c2 = 4u * nit + ntail - c0 - c1;

    #pragma unroll
    for (int off = 16; off > 0; off >>= 1) {
        s0 += __shfl_down_sync(0xffffffffu, s0, off);
        s1 += __shfl_down_sync(0xffffffffu, s1, off);
        s2 += __shfl_down_sync(0xffffffffu, s2, off);
        c0 += __shfl_down_sync(0xffffffffu, c0, off);
        c1 += __shfl_down_sync(0xffffffffu, c1, off);
        c2 += __shfl_down_sync(0xffffffffu, c2, off);
    }

    __shared__ float    bs[3];
    __shared__ unsigned bc[3];
    if (threadIdx.x < 3) { bs[threadIdx.x] = 0.f; bc[threadIdx.x] = 0u; }
    __syncthreads();
    if ((threadIdx.x & 31) == 0) {
        atomicAdd(&bs[0], s0); atomicAdd(&bs[1], s1); atomicAdd(&bs[2], s2);
        atomicAdd(&bc[0], c0); atomicAdd(&bc[1], c1); atomicAdd(&bc[2], c2);
    }
    __syncthreads();
    if (threadIdx.x < 3) {
        atomicAdd(&g_sums[threadIdx.x], (double)bs[threadIdx.x]);
        atomicAdd(&g_cnts[threadIdx.x], (unsigned long long)bc[threadIdx.x]);
    }
}

// ---------------------------------------------------------------------------
// Kernel 2: TMA bulk-store scatter (R8 structure) launched with PDL.
// Prologue (first-tile inst prefetch) runs BEFORE the grid-dependency sync;
// everything touching g_sums/g_cnts/out runs after it.
// ---------------------------------------------------------------------------
__global__ __launch_bounds__(256)
void iwap_scatter_kernel(const int4*  __restrict__ inst4,
                         char* __restrict__ outBytes,
                         const int*   __restrict__ inst,
                         const float* __restrict__ feats,
                         float* __restrict__ out,
                         int npix) {
    __shared__ float4 obuf[2][768];                  // 2 x 12KB staging
    __shared__ float  smean[3];

    const int t     = threadIdx.x;
    const int ntile = npix >> 10;

    // --- Pre-sync prologue: prefetch first tile's classes (input-only). ---
    int tile = blockIdx.x;
    int4 v = make_int4(0, 0, 0, 0);
    if (tile < ntile) v = __ldg(&inst4[(tile << 8) + t]);

    // --- Wait for the reduce grid to fully complete. ---
    cudaGridDependencySynchronize();

    // Inline finalize: means from global accumulators (L2-resident).
    if (t < 3) {
        double cnt = 3.0 * (double)g_cnts[t];
        smean[t] = (cnt > 0.0) ? (float)(g_sums[t] / cnt) : 0.0f;
    }
    __syncthreads();
    const float m0 = smean[0], m1 = smean[1], m2 = smean[2];

    // Self-restore: last block to consume the means zeroes the accumulators.
    if (t == 0) {
        unsigned prev = atomicAdd(&g_done, 1u);
        if (prev == gridDim.x - 1u) {
            g_sums[0] = 0.0; g_sums[1] = 0.0; g_sums[2] = 0.0;
            g_cnts[0] = 0ull; g_cnts[1] = 0ull; g_cnts[2] = 0ull;
            g_done    = 0u;
        }
    }

    int iter = 0;
    while (tile < ntile) {
        const int nextTile = tile + gridDim.x;
        const int b        = iter & 1;

        // Ensure the bulk store that last read obuf[b] has finished reading.
        if (t == 0) {
            asm volatile("cp.async.bulk.wait_group.read 1;" ::: "memory");
        }
        __syncthreads();

        // Compose this thread's 12 output floats (pixels 4t..4t+3 of tile).
        float ma = (v.x == 0) ? m0 : ((v.x == 1) ? m1 : m2);
        float mb = (v.y == 0) ? m0 : ((v.y == 1) ? m1 : m2);
        float mc = (v.z == 0) ? m0 : ((v.z == 1) ? m1 : m2);
        float md = (v.w == 0) ? m0 : ((v.w == 1) ? m1 : m2);
        float4 f0 = make_float4(ma, ma, ma, mb);
        float4 f1 = make_float4(mb, mb, mc, mc);
        float4 f2 = make_float4(mc, md, md, md);

        if (((unsigned)v.x >= 3u) | ((unsigned)v.y >= 3u) |
            ((unsigned)v.z >= 3u) | ((unsigned)v.w >= 3u)) {
            // Essentially-impossible path: out-of-range class keeps feats.
            float tmp[12] = {f0.x, f0.y, f0.z, f0.w, f1.x, f1.y,
                             f1.z, f1.w, f2.x, f2.y, f2.z, f2.w};
            int cs[4] = {v.x, v.y, v.z, v.w};
            size_t fb = ((size_t)(tile << 10) + 4 * t) * 3;
            for (int q = 0; q < 4; q++) {
                if ((unsigned)cs[q] >= 3u) {
                    tmp[3 * q + 0] = feats[fb + 3 * q + 0];
                    tmp[3 * q + 1] = feats[fb + 3 * q + 1];
                    tmp[3 * q + 2] = feats[fb + 3 * q + 2];
                }
            }
            f0 = make_float4(tmp[0], tmp[1], tmp[2],  tmp[3]);
            f1 = make_float4(tmp[4], tmp[5], tmp[6],  tmp[7]);
            f2 = make_float4(tmp[8], tmp[9], tmp[10], tmp[11]);
        }

        obuf[b][3 * t + 0] = f0;
        obuf[b][3 * t + 1] = f1;
        obuf[b][3 * t + 2] = f2;

        // Prefetch next tile's classes while smem settles.
        int4 vn = make_int4(0, 0, 0, 0);
        if (nextTile < ntile) vn = __ldg(&inst4[(nextTile << 8) + t]);

        __syncthreads();

        if (t == 0) {
            asm volatile("fence.proxy.async.shared::cta;" ::: "memory");
            const char* gdst = outBytes + (size_t)tile * 12288u;
            uint32_t    ssrc = smem_u32(&obuf[b][0]);
            asm volatile(
                "cp.async.bulk.global.shared::cta.bulk_group [%0], [%1], %2;"
                :: "l"(gdst), "r"(ssrc), "r"(12288u) : "memory");
            asm volatile("cp.async.bulk.commit_group;" ::: "memory");
        }

        v    = vn;
        tile = nextTile;
        iter++;
    }

    // Drain all outstanding bulk stores before smem is deallocated.
    if (t == 0) {
        asm volatile("cp.async.bulk.wait_group 0;" ::: "memory");
    }

    // Tail pixels (npix not divisible by 1024): block 0, scalar.
    if (blockIdx.x == 0) {
        for (int p = (ntile << 10) + t; p < npix; p += blockDim.x) {
            int c = inst[p];
            if ((unsigned)c < 3u) {
                float m = (c == 0) ? m0 : ((c == 1) ? m1 : m2);
                out[3 * p] = m; out[3 * p + 1] = m; out[3 * p + 2] = m;
            } else {
                out[3 * p]     = feats[3 * p];
                out[3 * p + 1] = feats[3 * p + 1];
                out[3 * p + 2] = feats[3 * p + 2];
            }
        }
    }
}

// ---------------------------------------------------------------------------
extern "C" void kernel_launch(void* const* d_in, const int* in_sizes, int n_in,
                              void* d_out, int out_size) {
    const float* feats = (const float*)d_in[0];   // [16,1024,1024,3] f32
    const int*   inst  = (const int*)d_in[1];     // [16,1024,1024,1] i32
    float*       out   = (float*)d_out;

    const int npix   = in_sizes[1];               // 16*1024*1024
    const int nitems = npix >> 2;                 // 4 pixels per reduce item

    const float4* feats4 = (const float4*)feats;
    const int4*   inst4  = (const int4*)inst;

    const int rblocks = 1216;                     // 8 per SM, single wave
    iwap_reduce_kernel<<<rblocks, 256>>>(feats4, inst4, feats, inst, nitems, npix);

    // Scatter launched with programmatic dependent launch: its block dispatch
    // + inst prefetch overlap the reduce's epilogue; the device-side
    // cudaGridDependencySynchronize() enforces the data dependency.
    {
        cudaLaunchConfig_t cfg = {};
        cfg.gridDim  = dim3(1216, 1, 1);
        cfg.blockDim = dim3(256, 1, 1);
        cudaLaunchAttribute attr[1];
        attr[0].id = cudaLaunchAttributeProgrammaticStreamSerialization;
        attr[0].val.programmaticStreamSerializationAllowed = 1;
        cfg.attrs    = attr;
        cfg.numAttrs = 1;
        cudaLaunchKernelEx(&cfg, iwap_scatter_kernel,
                           inst4, (char*)out, inst, feats, out, npix);
    }
}

// round 14
// speedup vs baseline: 1.0080x; 1.0080x over previous
#include <cuda_runtime.h>
#include <cuda_bf16.h>
#include <cstdint>

// Scratch (no allocation allowed). Zero-initialized at module load; the
// scatter's last block restores zeros each call (deterministic replays).
__device__ double             g_sums[3];
__device__ unsigned long long g_cnts[3];
__device__ unsigned           g_done;

__device__ __forceinline__ uint32_t smem_u32(const void* p) {
    uint32_t a;
    asm("{ .reg .u64 t; cvta.to.shared.u64 t, %1; cvt.u32.u64 %0, t; }"
        : "=r"(a) : "l"(p));
    return a;
}

// ---------------------------------------------------------------------------
// Per-item accumulate: 4 pixels (1 int4 + 3 float4).
// ---------------------------------------------------------------------------
__device__ __forceinline__ void acc_item(const int4& cls,
                                         const float4& a, const float4& b,
                                         const float4& d,
                                         float& ptot, float& s0, float& s1,
                                         unsigned& c0, unsigned& c1) {
    float p0 = a.x + a.y + a.z;
    float p1 = a.w + b.x + b.y;
    float p2 = b.z + b.w + d.x;
    float p3 = d.y + d.z + d.w;
    ptot += (p0 + p1) + (p2 + p3);
    s0 += (cls.x == 0) ? p0 : 0.f;  c0 += (cls.x == 0);
    s1 += (cls.x == 1) ? p0 : 0.f;  c1 += (cls.x == 1);
    s0 += (cls.y == 0) ? p1 : 0.f;  c0 += (cls.y == 0);
    s1 += (cls.y == 1) ? p1 : 0.f;  c1 += (cls.y == 1);
    s0 += (cls.z == 0) ? p2 : 0.f;  c0 += (cls.z == 0);
    s1 += (cls.z == 1) ? p2 : 0.f;  c1 += (cls.z == 1);
    s0 += (cls.w == 0) ? p3 : 0.f;  c0 += (cls.w == 0);
    s1 += (cls.w == 1) ? p3 : 0.f;  c1 += (cls.w == 1);
}

// ---------------------------------------------------------------------------
// Kernel 1: grid-stride reduction, 2x unrolled, front-batched loads.
// Only class 0/1 accumulated explicitly; class 2 derived from totals
// (classes partition all pixels). feats streamed (.cs) so inst lines
// survive in L2 for the scatter. fp32 per-thread accumulation; block
// partials promoted to double for the global atomics.
// ---------------------------------------------------------------------------
__global__ __launch_bounds__(256)
void iwap_reduce_kernel(const float4* __restrict__ feats4,
                        const int4*  __restrict__ inst4,
                        const float* __restrict__ feats,
                        const int*   __restrict__ inst,
                        int nitems, int npix) {
    float    ptot = 0.f, s0 = 0.f, s1 = 0.f;
    unsigned c0 = 0, c1 = 0, nit = 0;

    const int S = gridDim.x * blockDim.x;
    int i = blockIdx.x * blockDim.x + threadIdx.x;

    for (; i + S < nitems; i += 2 * S) {
        int4   clsA = __ldg(&inst4[i]);
        int4   clsB = __ldg(&inst4[i + S]);
        float4 a0 = __ldcs(&feats4[3 * i + 0]);
        float4 a1 = __ldcs(&feats4[3 * i + 1]);
        float4 a2 = __ldcs(&feats4[3 * i + 2]);
        float4 b0 = __ldcs(&feats4[3 * (i + S) + 0]);
        float4 b1 = __ldcs(&feats4[3 * (i + S) + 1]);
        float4 b2 = __ldcs(&feats4[3 * (i + S) + 2]);
        acc_item(clsA, a0, a1, a2, ptot, s0, s1, c0, c1);
        acc_item(clsB, b0, b1, b2, ptot, s0, s1, c0, c1);
        nit += 2;
    }
    if (i < nitems) {
        int4   cls = __ldg(&inst4[i]);
        float4 a0 = __ldcs(&feats4[3 * i + 0]);
        float4 a1 = __ldcs(&feats4[3 * i + 1]);
        float4 a2 = __ldcs(&feats4[3 * i + 2]);
        acc_item(cls, a0, a1, a2, ptot, s0, s1, c0, c1);
        nit += 1;
    }

    // Tail pixels (npix not divisible by 4) by thread 0 of block 0.
    unsigned ntail = 0;
    if (blockIdx.x == 0 && threadIdx.x == 0) {
        for (int p = nitems * 4; p < npix; p++) {
            int   c  = inst[p];
            float ps = feats[3 * p] + feats[3 * p + 1] + feats[3 * p + 2];
            ptot += ps; ntail++;
            if      (c == 0) { s0 += ps; c0++; }
            else if (c == 1) { s1 += ps; c1++; }
        }
    }

    float    s2 = ptot - s0 - s1;
    unsigned c2 = 4u * nit + ntail - c0 - c1;

    #pragma unroll
    for (int off = 16; off > 0; off >>= 1) {
        s0 += __shfl_down_sync(0xffffffffu, s0, off);
        s1 += __shfl_down_sync(0xffffffffu, s1, off);
        s2 += __shfl_down_sync(0xffffffffu, s2, off);
        c0 += __shfl_down_sync(0xffffffffu, c0, off);
        c1 += __shfl_down_sync(0xffffffffu, c1, off);
        c2 += __shfl_down_sync(0xffffffffu, c2, off);
    }

    __shared__ float    bs[3];
    __shared__ unsigned bc[3];
    if (threadIdx.x < 3) { bs[threadIdx.x] = 0.f; bc[threadIdx.x] = 0u; }
    __syncthreads();
    if ((threadIdx.x & 31) == 0) {
        atomicAdd(&bs[0], s0); atomicAdd(&bs[1], s1); atomicAdd(&bs[2], s2);
        atomicAdd(&bc[0], c0); atomicAdd(&bc[1], c1); atomicAdd(&bc[2], c2);
    }
    __syncthreads();
    if (threadIdx.x < 3) {
        atomicAdd(&g_sums[threadIdx.x], (double)bs[threadIdx.x]);
        atomicAdd(&g_cnts[threadIdx.x], (unsigned long long)bc[threadIdx.x]);
    }
}

// ---------------------------------------------------------------------------
// Kernel 2: TMA bulk-store scatter (best measured configuration).
// Persistent 1216 blocks; per 1024-pixel tile each thread composes its 12
// output floats (fixed pattern, no division) into a smem staging buffer;
// one elected thread emits the 12KB tile as a single cp.async.bulk
// shared->global store, double-buffered so the TMA engine drains stores
// while the SM composes subsequent tiles. Inline finalize (threads 0-2) +
// self-restoring accumulators (last block re-zeros for the next replay).
// ---------------------------------------------------------------------------
__global__ __launch_bounds__(256)
void iwap_scatter_kernel(const int4*  __restrict__ inst4,
                         char* __restrict__ outBytes,
                         const int*   __restrict__ inst,
                         const float* __restrict__ feats,
                         float* __restrict__ out,
                         int npix) {
    __shared__ float4 obuf[2][768];                  // 2 x 12KB staging
    __shared__ float  smean[3];

    const int t = threadIdx.x;

    // Inline finalize: means from global accumulators (L2-resident).
    if (t < 3) {
        double cnt = 3.0 * (double)g_cnts[t];        // count incl. channels
        smean[t] = (cnt > 0.0) ? (float)(g_sums[t] / cnt) : 0.0f;
    }
    __syncthreads();
    const float m0 = smean[0], m1 = smean[1], m2 = smean[2];

    // Self-restore: last block to consume the means zeroes the accumulators.
    if (t == 0) {
        unsigned prev = atomicAdd(&g_done, 1u);
        if (prev == gridDim.x - 1u) {
            g_sums[0] = 0.0; g_sums[1] = 0.0; g_sums[2] = 0.0;
            g_cnts[0] = 0ull; g_cnts[1] = 0ull; g_cnts[2] = 0ull;
            g_done    = 0u;
        }
    }

    const int ntile = npix >> 10;

    int tile = blockIdx.x;
    int4 v = make_int4(0, 0, 0, 0);
    if (tile < ntile) v = __ldg(&inst4[(tile << 8) + t]);

    int iter = 0;
    while (tile < ntile) {
        const int nextTile = tile + gridDim.x;
        const int b        = iter & 1;

        // Ensure the bulk store that last read obuf[b] has finished reading.
        if (t == 0) {
            asm volatile("cp.async.bulk.wait_group.read 1;" ::: "memory");
        }
        __syncthreads();

        // Compose this thread's 12 output floats (pixels 4t..4t+3 of tile).
        float ma = (v.x == 0) ? m0 : ((v.x == 1) ? m1 : m2);
        float mb = (v.y == 0) ? m0 : ((v.y == 1) ? m1 : m2);
        float mc = (v.z == 0) ? m0 : ((v.z == 1) ? m1 : m2);
        float md = (v.w == 0) ? m0 : ((v.w == 1) ? m1 : m2);
        float4 f0 = make_float4(ma, ma, ma, mb);
        float4 f1 = make_float4(mb, mb, mc, mc);
        float4 f2 = make_float4(mc, md, md, md);

        if (((unsigned)v.x >= 3u) | ((unsigned)v.y >= 3u) |
            ((unsigned)v.z >= 3u) | ((unsigned)v.w >= 3u)) {
            // Essentially-impossible path: out-of-range class keeps feats.
            float tmp[12] = {f0.x, f0.y, f0.z, f0.w, f1.x, f1.y,
                             f1.z, f1.w, f2.x, f2.y, f2.z, f2.w};
            int cs[4] = {v.x, v.y, v.z, v.w};
            size_t fb = ((size_t)(tile << 10) + 4 * t) * 3;
            for (int q = 0; q < 4; q++) {
                if ((unsigned)cs[q] >= 3u) {
                    tmp[3 * q + 0] = feats[fb + 3 * q + 0];
                    tmp[3 * q + 1] = feats[fb + 3 * q + 1];
                    tmp[3 * q + 2] = feats[fb + 3 * q + 2];
                }
            }
            f0 = make_float4(tmp[0], tmp[1], tmp[2],  tmp[3]);
            f1 = make_float4(tmp[4], tmp[5], tmp[6],  tmp[7]);
            f2 = make_float4(tmp[8], tmp[9], tmp[10], tmp[11]);
        }

        obuf[b][3 * t + 0] = f0;
        obuf[b][3 * t + 1] = f1;
        obuf[b][3 * t + 2] = f2;

        // Prefetch next tile's classes while smem settles.
        int4 vn = make_int4(0, 0, 0, 0);
        if (nextTile < ntile) vn = __ldg(&inst4[(nextTile << 8) + t]);

        __syncthreads();

        if (t == 0) {
            asm volatile("fence.proxy.async.shared::cta;" ::: "memory");
            const char* gdst = outBytes + (size_t)tile * 12288u;
            uint32_t    ssrc = smem_u32(&obuf[b][0]);
            asm volatile(
                "cp.async.bulk.global.shared::cta.bulk_group [%0], [%1], %2;"
                :: "l"(gdst), "r"(ssrc), "r"(12288u) : "memory");
            asm volatile("cp.async.bulk.commit_group;" ::: "memory");
        }

        v    = vn;
        tile = nextTile;
        iter++;
    }

    // Drain all outstanding bulk stores before smem is deallocated.
    if (t == 0) {
        asm volatile("cp.async.bulk.wait_group 0;" ::: "memory");
    }

    // Tail pixels (npix not divisible by 1024): block 0, scalar.
    if (blockIdx.x == 0) {
        for (int p = (ntile << 10) + t; p < npix; p += blockDim.x) {
            int c = inst[p];
            if ((unsigned)c < 3u) {
                float m = (c == 0) ? m0 : ((c == 1) ? m1 : m2);
                out[3 * p] = m; out[3 * p + 1] = m; out[3 * p + 2] = m;
            } else {
                out[3 * p]     = feats[3 * p];
                out[3 * p + 1] = feats[3 * p + 1];
                out[3 * p + 2] = feats[3 * p + 2];
            }
        }
    }
}

// ---------------------------------------------------------------------------
extern "C" void kernel_launch(void* const* d_in, const int* in_sizes, int n_in,
                              void* d_out, int out_size) {
    const float* feats = (const float*)d_in[0];   // [16,1024,1024,3] f32
    const int*   inst  = (const int*)d_in[1];     // [16,1024,1024,1] i32
    float*       out   = (float*)d_out;

    const int npix   = in_sizes[1];               // 16*1024*1024
    const int nitems = npix >> 2;                 // 4 pixels per reduce item

    const float4* feats4 = (const float4*)feats;
    const int4*   inst4  = (const int4*)inst;

    const int rblocks = 1216;                     // 8 per SM, single wave
    iwap_reduce_kernel<<<rblocks, 256>>>(feats4, inst4, feats, inst, nitems, npix);

    const int sblocks = 1216;                     // persistent TMA-store scatter
    iwap_scatter_kernel<<<sblocks, 256>>>(inst4, (char*)out, inst, feats, out, npix);
}